// round 1
// baseline (speedup 1.0000x reference)
#include <cuda_runtime.h>
#include <cuda_bf16.h>

// EdgePredictor: out[e] = sigmoid(relu(relu([x[src]|x[dst]|attr] @ W1 + b1) @ W2 + b2) @ W3 + b3)
// E = 1M edges, HID = 128. Persistent-block fp32 register-tiled GEMM, weights in smem.

#define THREADS 256
#define TILE_E 128
// smem float offsets
#define OFF_W1   0        // 257*128 = 32896
#define OFF_HS   32896    // 128*128 = 16384 (gather buffer, then h1 buffer)
#define OFF_W2   49280    // 128*32 = 4096
#define OFF_B1   53376    // 128
#define OFF_B2   53504    // 32
#define OFF_W3   53536    // 32
#define OFF_ATTR 53568    // 128
#define OFF_SRC  53696    // 128 ints
#define OFF_DST  53824    // 128 ints
#define SMEM_FLOATS 53952
#define SMEM_BYTES (SMEM_FLOATS * 4)  // 215808

__global__ __launch_bounds__(THREADS, 1)
void edge_mlp_kernel(const float* __restrict__ x,
                     const int* __restrict__ ei,
                     const float* __restrict__ ea,
                     const float* __restrict__ W1g, const float* __restrict__ b1g,
                     const float* __restrict__ W2g, const float* __restrict__ b2g,
                     const float* __restrict__ W3g, const float* __restrict__ b3g,
                     float* __restrict__ out, int nE)
{
    extern __shared__ float s[];
    float* W1s  = s + OFF_W1;
    float* Hs   = s + OFF_HS;
    float* W2s  = s + OFF_W2;
    float* b1s  = s + OFF_B1;
    float* b2s  = s + OFF_B2;
    float* W3s  = s + OFF_W3;
    float* attrS = s + OFF_ATTR;
    int*   srcS = (int*)(s + OFF_SRC);
    int*   dstS = (int*)(s + OFF_DST);

    const int tx = threadIdx.x;

    // Stage weights once per block (persistent blocks).
    for (int i = tx; i < 257 * 128; i += THREADS) W1s[i] = W1g[i];
    for (int i = tx; i < 128 * 32;  i += THREADS) W2s[i] = W2g[i];
    if (tx < 128) b1s[tx] = b1g[tx];
    if (tx < 32) { b2s[tx] = b2g[tx]; W3s[tx] = W3g[tx]; }
    const float b3v = b3g[0];
    __syncthreads();

    // Layer-1 mapping: 128 edges x 128 outs; thread = 8 edges x 8 outs.
    const int oG  = tx & 15;   // 16 groups * 8 outs
    const int eG  = tx >> 4;   // 16 groups * 8 edges
    // Layer-2 mapping: 128 edges x 32 outs; thread = 4 edges x 4 outs.
    const int oG2 = tx & 7;    // 8 groups * 4 outs
    const int eG2 = tx >> 3;   // 32 groups * 4 edges

    const int nTiles = (nE + TILE_E - 1) >> 7;
    const float4* x4 = (const float4*)x;

    for (int tile = blockIdx.x; tile < nTiles; tile += gridDim.x) {
        const int base = tile << 7;

        if (tx < TILE_E) {
            int e = base + tx;
            bool v = (e < nE);
            srcS[tx]  = v ? ei[e] : 0;
            dstS[tx]  = v ? ei[nE + e] : 0;
            attrS[tx] = v ? ea[e] : 0.f;
        }
        __syncthreads();

        float acc[8][8];
        #pragma unroll
        for (int i = 0; i < 8; i++)
            #pragma unroll
            for (int j = 0; j < 8; j++) acc[i][j] = 0.f;

        // Two gather chunks: c=0 -> x[src] vs W1 rows 0..127, c=1 -> x[dst] vs rows 128..255
        #pragma unroll
        for (int c = 0; c < 2; c++) {
            const int* idxS = c ? dstS : srcS;
            #pragma unroll
            for (int r = 0; r < 16; r++) {
                int idx = r * THREADS + tx;
                int e = idx >> 5, q = idx & 31;           // 32 float4 per 128-f32 row
                ((float4*)Hs)[e * 32 + q] = x4[idxS[e] * 32 + q];
            }
            __syncthreads();

            const float* W1c = W1s + c * 128 * 128;
            for (int k4 = 0; k4 < 32; k4++) {
                float ev[8][4];
                #pragma unroll
                for (int i = 0; i < 8; i++) {
                    float4 t = ((const float4*)Hs)[(eG * 8 + i) * 32 + k4];
                    ev[i][0] = t.x; ev[i][1] = t.y; ev[i][2] = t.z; ev[i][3] = t.w;
                }
                #pragma unroll
                for (int s4 = 0; s4 < 4; s4++) {
                    const float4* wp = (const float4*)(W1c + (k4 * 4 + s4) * 128);
                    float4 w0 = wp[oG * 2], w1 = wp[oG * 2 + 1];
                    float wv[8] = {w0.x, w0.y, w0.z, w0.w, w1.x, w1.y, w1.z, w1.w};
                    #pragma unroll
                    for (int i = 0; i < 8; i++)
                        #pragma unroll
                        for (int j = 0; j < 8; j++)
                            acc[i][j] = fmaf(ev[i][s4], wv[j], acc[i][j]);
                }
            }
            __syncthreads();
        }

        // k = 256: edge_attr column against W1 row 256
        {
            const float4* wp = (const float4*)(W1s + 256 * 128);
            float4 w0 = wp[oG * 2], w1 = wp[oG * 2 + 1];
            float wv[8] = {w0.x, w0.y, w0.z, w0.w, w1.x, w1.y, w1.z, w1.w};
            #pragma unroll
            for (int i = 0; i < 8; i++) {
                float a = attrS[eG * 8 + i];
                #pragma unroll
                for (int j = 0; j < 8; j++)
                    acc[i][j] = fmaf(a, wv[j], acc[i][j]);
            }
        }

        // bias + relu -> Hs (gather buffer is free: both chunks consumed, post-sync)
        #pragma unroll
        for (int i = 0; i < 8; i++) {
            float h[8];
            #pragma unroll
            for (int j = 0; j < 8; j++) {
                float v = acc[i][j] + b1s[oG * 8 + j];
                h[j] = v > 0.f ? v : 0.f;
            }
            float4* dst0 = (float4*)(Hs + (eG * 8 + i) * 128 + oG * 8);
            dst0[0] = make_float4(h[0], h[1], h[2], h[3]);
            dst0[1] = make_float4(h[4], h[5], h[6], h[7]);
        }
        __syncthreads();

        // Layer 2: [128 x 128] @ [128 x 32]
        float acc2[4][4];
        #pragma unroll
        for (int i = 0; i < 4; i++)
            #pragma unroll
            for (int j = 0; j < 4; j++) acc2[i][j] = 0.f;

        for (int k4 = 0; k4 < 32; k4++) {
            float ev[4][4];
            #pragma unroll
            for (int i = 0; i < 4; i++) {
                float4 t = ((const float4*)Hs)[(eG2 * 4 + i) * 32 + k4];
                ev[i][0] = t.x; ev[i][1] = t.y; ev[i][2] = t.z; ev[i][3] = t.w;
            }
            #pragma unroll
            for (int s4 = 0; s4 < 4; s4++) {
                float4 w = ((const float4*)(W2s + (k4 * 4 + s4) * 32))[oG2];
                float wv[4] = {w.x, w.y, w.z, w.w};
                #pragma unroll
                for (int i = 0; i < 4; i++)
                    #pragma unroll
                    for (int j = 0; j < 4; j++)
                        acc2[i][j] = fmaf(ev[i][s4], wv[j], acc2[i][j]);
            }
        }

        // Layer 3: relu(h2) . W3, 8-lane reduce, sigmoid
        float part[4];
        #pragma unroll
        for (int i = 0; i < 4; i++) {
            float p = 0.f;
            #pragma unroll
            for (int j = 0; j < 4; j++) {
                float h = acc2[i][j] + b2s[oG2 * 4 + j];
                h = fmaxf(h, 0.f);
                p = fmaf(h, W3s[oG2 * 4 + j], p);
            }
            part[i] = p;
        }
        #pragma unroll
        for (int i = 0; i < 4; i++) {
            part[i] += __shfl_xor_sync(0xffffffffu, part[i], 1, 8);
            part[i] += __shfl_xor_sync(0xffffffffu, part[i], 2, 8);
            part[i] += __shfl_xor_sync(0xffffffffu, part[i], 4, 8);
        }
        if (oG2 == 0) {
            #pragma unroll
            for (int i = 0; i < 4; i++) {
                int e = base + eG2 * 4 + i;
                if (e < nE) {
                    float z = part[i] + b3v;
                    out[e] = 1.f / (1.f + __expf(-z));
                }
            }
        }
        __syncthreads();  // protect Hs/srcS before next tile
    }
}

extern "C" void kernel_launch(void* const* d_in, const int* in_sizes, int n_in,
                              void* d_out, int out_size)
{
    const float* x  = (const float*)d_in[0];
    const int*   ei = (const int*)d_in[1];
    const float* ea = (const float*)d_in[2];
    const float* W1 = (const float*)d_in[3];
    const float* b1 = (const float*)d_in[4];
    const float* W2 = (const float*)d_in[5];
    const float* b2 = (const float*)d_in[6];
    const float* W3 = (const float*)d_in[7];
    const float* b3 = (const float*)d_in[8];
    float* out = (float*)d_out;
    const int nE = out_size;

    cudaFuncSetAttribute(edge_mlp_kernel,
                         cudaFuncAttributeMaxDynamicSharedMemorySize, SMEM_BYTES);
    edge_mlp_kernel<<<148, THREADS, SMEM_BYTES>>>(x, ei, ea, W1, b1, W2, b2, W3, b3, out, nE);
}

// round 3
// speedup vs baseline: 3.1983x; 3.1983x over previous
#include <cuda_runtime.h>
#include <cstdint>

// EdgePredictor via base-ISA tensor cores: mma.sync.m16n8k8 tf32 + ldmatrix.
// Per 128-edge tile: L1 GEMM [128x257]x[257x128] (two K=128 halves, src/dst gathers),
// epilogue relu -> h1 in smem, L2 GEMM [128x128]x[128x32], in-warp L3 dot + sigmoid.
// Weights staged once (transposed, tf32) per persistent CTA; 148 CTAs x 256 threads.

#define THREADS 256
#define SA 132   // A row stride (words): 128 + 4 pad -> conflict-free LDSM
#define S1 260   // W1t row stride (words): 256 + 4
#define S2 132   // W2t row stride

#define OFF_W1T  0u        // [128 n][260] tf32 : 133120 B
#define OFF_A    133120u   // [128 m][132] tf32 : 67584 B (feats, then h1)
#define OFF_W2T  200704u   // [32 n][132] tf32 : 16896 B
#define OFF_B1   217600u   // 128 f32
#define OFF_R256 218112u   // 128 f32 (W1 row 256 = attr weights)
#define OFF_B2   218624u   // 32 f32
#define OFF_W3   218752u   // 32 f32
#define OFF_ATTR 218880u   // 128 f32
#define OFF_SRC  219392u   // 128 i32
#define OFF_DST  219904u   // 128 i32
#define SMEM_BYTES 220416

__device__ __forceinline__ uint32_t smem_u32(const void* p) {
    uint32_t a;
    asm("{ .reg .u64 t; cvta.to.shared.u64 t, %1; cvt.u32.u64 %0, t; }" : "=r"(a) : "l"(p));
    return a;
}
__device__ __forceinline__ uint32_t f2tf32(float f) {
    uint32_t r;
    asm("cvt.rn.tf32.f32 %0, %1;" : "=r"(r) : "f"(f));
    return r;
}
__device__ __forceinline__ void ldsm4(uint32_t* r, uint32_t a) {
    asm volatile("ldmatrix.sync.aligned.m8n8.x4.shared.b16 {%0,%1,%2,%3}, [%4];"
                 : "=r"(r[0]), "=r"(r[1]), "=r"(r[2]), "=r"(r[3]) : "r"(a));
}
__device__ __forceinline__ void ldsm2(uint32_t* r, uint32_t a) {
    asm volatile("ldmatrix.sync.aligned.m8n8.x2.shared.b16 {%0,%1}, [%2];"
                 : "=r"(r[0]), "=r"(r[1]) : "r"(a));
}
__device__ __forceinline__ void mma8(float* c, const uint32_t* a, const uint32_t* b) {
    asm volatile("mma.sync.aligned.m16n8k8.row.col.f32.tf32.tf32.f32 "
                 "{%0,%1,%2,%3}, {%4,%5,%6,%7}, {%8,%9}, {%0,%1,%2,%3};"
                 : "+f"(c[0]), "+f"(c[1]), "+f"(c[2]), "+f"(c[3])
                 : "r"(a[0]), "r"(a[1]), "r"(a[2]), "r"(a[3]), "r"(b[0]), "r"(b[1]));
}

__global__ __launch_bounds__(THREADS, 1)
void edge_mlp_hmma(const float* __restrict__ x,
                   const int* __restrict__ ei,
                   const float* __restrict__ ea,
                   const float* __restrict__ W1g, const float* __restrict__ b1g,
                   const float* __restrict__ W2g, const float* __restrict__ b2g,
                   const float* __restrict__ W3g, const float* __restrict__ b3g,
                   float* __restrict__ out, int nE)
{
    extern __shared__ char smem[];
    const uint32_t sb = smem_u32(smem);
    const int tx = threadIdx.x;
    const int w  = tx >> 5;
    const int l  = tx & 31;

    uint32_t* W1t = (uint32_t*)(smem + OFF_W1T);
    uint32_t* W2t = (uint32_t*)(smem + OFF_W2T);
    float* b1s   = (float*)(smem + OFF_B1);
    float* r256s = (float*)(smem + OFF_R256);
    float* b2s   = (float*)(smem + OFF_B2);
    float* W3s   = (float*)(smem + OFF_W3);
    float* attrS = (float*)(smem + OFF_ATTR);
    int*   srcS  = (int*)(smem + OFF_SRC);
    int*   dstS  = (int*)(smem + OFF_DST);

    // ---- one-time weight staging (tf32, transposed) ----
    for (int idx = tx; idx < 257 * 128; idx += THREADS) {
        int k = idx >> 7, n = idx & 127;
        float v = W1g[idx];
        if (k < 256) W1t[n * S1 + k] = f2tf32(v);
        else         r256s[n] = v;                  // attr weight row, kept fp32
    }
    for (int idx = tx; idx < 128 * 32; idx += THREADS) {
        int k = idx >> 5, n = idx & 31;
        W2t[n * S2 + k] = f2tf32(W2g[idx]);
    }
    if (tx < 128) b1s[tx] = b1g[tx];
    if (tx < 32)  { b2s[tx] = b2g[tx]; W3s[tx] = W3g[tx]; }
    const float b3v = b3g[0];
    __syncthreads();

    // ---- per-lane fragment address bases ----
    const int g = l >> 2, t4 = l & 3;
    const int aSel = l & 15;                 // ldmatrix x4 lane -> row-in-16
    const int aColB = (l >> 4) * 16;         // +4 cols (bytes) for matrices 2,3
    const int bRow = l & 7;
    const int bColB = ((l >> 3) & 1) * 16;

    // layer-1: warp tile 32m x 64n
    const int m0w = (w & 3) * 32;
    const int n0w = (w >> 2) * 64;
    const uint32_t aBase0 = sb + OFF_A + (uint32_t)(m0w + aSel) * (SA * 4) + aColB;
    const uint32_t aBase1 = aBase0 + 16 * SA * 4;
    const uint32_t bBase1 = sb + OFF_W1T + (uint32_t)(n0w + bRow) * (S1 * 4) + bColB;
    // layer-2: warp tile 16m x 32n
    const int m0w2 = w * 16;
    const uint32_t aBase2 = sb + OFF_A + (uint32_t)(m0w2 + aSel) * (SA * 4) + aColB;
    const uint32_t bBase2 = sb + OFF_W2T + (uint32_t)bRow * (S2 * 4) + bColB;

    const float4* x4 = (const float4*)x;
    const int nTiles = (nE + 127) >> 7;

    for (int tile = blockIdx.x; tile < nTiles; tile += gridDim.x) {
        const int base = tile << 7;

        if (tx < 128) {
            int e = base + tx;
            bool v = (e < nE);
            srcS[tx]  = v ? ei[e] : 0;
            dstS[tx]  = v ? ei[nE + e] : 0;
            attrS[tx] = v ? ea[e] : 0.f;
        }
        __syncthreads();

        // ---- gather src -> A (row = r*8 + w, col-f4 = lane) ----
        #pragma unroll
        for (int r = 0; r < 16; r++) {
            int row = r * 8 + w;
            float4 ft = x4[srcS[row] * 32 + l];
            uint4 u = make_uint4(f2tf32(ft.x), f2tf32(ft.y), f2tf32(ft.z), f2tf32(ft.w));
            *(uint4*)(smem + OFF_A + (uint32_t)row * (SA * 4) + l * 16) = u;
        }
        __syncthreads();

        // ---- prefetch dst gather into registers (hidden behind half-0 MMA) ----
        float4 dbuf[16];
        #pragma unroll
        for (int r = 0; r < 16; r++)
            dbuf[r] = x4[dstS[r * 8 + w] * 32 + l];

        float acc[2][8][4];
        #pragma unroll
        for (int mi = 0; mi < 2; mi++)
            #pragma unroll
            for (int ni = 0; ni < 8; ni++)
                #pragma unroll
                for (int c = 0; c < 4; c++) acc[mi][ni][c] = 0.f;

        // ---- layer-1 half 0 (src features vs W1 rows 0..127) ----
        #pragma unroll 4
        for (int ks = 0; ks < 16; ks++) {
            uint32_t a0[4], a1[4];
            ldsm4(a0, aBase0 + ks * 32);
            ldsm4(a1, aBase1 + ks * 32);
            #pragma unroll
            for (int ni = 0; ni < 8; ni++) {
                uint32_t b[2];
                ldsm2(b, bBase1 + ni * (8 * S1 * 4) + ks * 32);
                mma8(acc[0][ni], a0, b);
                mma8(acc[1][ni], a1, b);
            }
        }
        __syncthreads();

        // ---- store dst features -> A ----
        #pragma unroll
        for (int r = 0; r < 16; r++) {
            int row = r * 8 + w;
            uint4 u = make_uint4(f2tf32(dbuf[r].x), f2tf32(dbuf[r].y),
                                 f2tf32(dbuf[r].z), f2tf32(dbuf[r].w));
            *(uint4*)(smem + OFF_A + (uint32_t)row * (SA * 4) + l * 16) = u;
        }
        __syncthreads();

        // ---- layer-1 half 1 (dst features vs W1 rows 128..255) ----
        #pragma unroll 4
        for (int ks = 0; ks < 16; ks++) {
            uint32_t a0[4], a1[4];
            ldsm4(a0, aBase0 + ks * 32);
            ldsm4(a1, aBase1 + ks * 32);
            #pragma unroll
            for (int ni = 0; ni < 8; ni++) {
                uint32_t b[2];
                ldsm2(b, bBase1 + ni * (8 * S1 * 4) + 512 + ks * 32);  // +128 k cols
                mma8(acc[0][ni], a0, b);
                mma8(acc[1][ni], a1, b);
            }
        }
        __syncthreads();   // all LDSM reads of A done before h1 overwrite

        // ---- epilogue 1: h1 = relu(D1 + attr*r256 + b1) -> A (tf32) ----
        {
            float aR[2][2];
            aR[0][0] = attrS[m0w + g];      aR[0][1] = attrS[m0w + 8 + g];
            aR[1][0] = attrS[m0w + 16 + g]; aR[1][1] = attrS[m0w + 24 + g];
            #pragma unroll
            for (int mi = 0; mi < 2; mi++) {
                int row0 = m0w + mi * 16 + g;
                #pragma unroll
                for (int ni = 0; ni < 8; ni++) {
                    int col = n0w + ni * 8 + 2 * t4;
                    float2 bb = *(const float2*)(b1s + col);
                    float2 rr = *(const float2*)(r256s + col);
                    float h0 = fmaxf(acc[mi][ni][0] + aR[mi][0] * rr.x + bb.x, 0.f);
                    float h1 = fmaxf(acc[mi][ni][1] + aR[mi][0] * rr.y + bb.y, 0.f);
                    float h2 = fmaxf(acc[mi][ni][2] + aR[mi][1] * rr.x + bb.x, 0.f);
                    float h3 = fmaxf(acc[mi][ni][3] + aR[mi][1] * rr.y + bb.y, 0.f);
                    uint2 u0 = make_uint2(f2tf32(h0), f2tf32(h1));
                    uint2 u1 = make_uint2(f2tf32(h2), f2tf32(h3));
                    *(uint2*)(smem + OFF_A + (uint32_t)row0 * (SA * 4) + col * 4) = u0;
                    *(uint2*)(smem + OFF_A + (uint32_t)(row0 + 8) * (SA * 4) + col * 4) = u1;
                }
            }
        }
        __syncthreads();

        // ---- layer 2: [128 x 128] @ [128 x 32] ----
        float acc2[4][4];
        #pragma unroll
        for (int ni = 0; ni < 4; ni++)
            #pragma unroll
            for (int c = 0; c < 4; c++) acc2[ni][c] = 0.f;

        #pragma unroll 4
        for (int ks = 0; ks < 16; ks++) {
            uint32_t a0[4];
            ldsm4(a0, aBase2 + ks * 32);
            #pragma unroll
            for (int ni = 0; ni < 4; ni++) {
                uint32_t b[2];
                ldsm2(b, bBase2 + ni * (8 * S2 * 4) + ks * 32);
                mma8(acc2[ni], a0, b);
            }
        }

        // ---- layer 3: relu(h2).W3 in-warp reduce + sigmoid ----
        {
            float p0 = 0.f, p1 = 0.f;
            #pragma unroll
            for (int ni = 0; ni < 4; ni++) {
                int col = ni * 8 + 2 * t4;
                float2 bb = *(const float2*)(b2s + col);
                float2 ww = *(const float2*)(W3s + col);
                p0 += fmaxf(acc2[ni][0] + bb.x, 0.f) * ww.x
                    + fmaxf(acc2[ni][1] + bb.y, 0.f) * ww.y;
                p1 += fmaxf(acc2[ni][2] + bb.x, 0.f) * ww.x
                    + fmaxf(acc2[ni][3] + bb.y, 0.f) * ww.y;
            }
            p0 += __shfl_xor_sync(0xffffffffu, p0, 1, 4);
            p0 += __shfl_xor_sync(0xffffffffu, p0, 2, 4);
            p1 += __shfl_xor_sync(0xffffffffu, p1, 1, 4);
            p1 += __shfl_xor_sync(0xffffffffu, p1, 2, 4);
            if (t4 == 0) {
                int e0 = base + m0w2 + g;
                int e1 = e0 + 8;
                if (e0 < nE) out[e0] = 1.f / (1.f + __expf(-(p0 + b3v)));
                if (e1 < nE) out[e1] = 1.f / (1.f + __expf(-(p1 + b3v)));
            }
        }
        __syncthreads();   // A + srcS reused next tile
    }
}

extern "C" void kernel_launch(void* const* d_in, const int* in_sizes, int n_in,
                              void* d_out, int out_size)
{
    const float* x  = (const float*)d_in[0];
    const int*   ei = (const int*)d_in[1];
    const float* ea = (const float*)d_in[2];
    const float* W1 = (const float*)d_in[3];
    const float* b1 = (const float*)d_in[4];
    const float* W2 = (const float*)d_in[5];
    const float* b2 = (const float*)d_in[6];
    const float* W3 = (const float*)d_in[7];
    const float* b3 = (const float*)d_in[8];
    float* out = (float*)d_out;
    const int nE = out_size;

    cudaFuncSetAttribute(edge_mlp_hmma,
                         cudaFuncAttributeMaxDynamicSharedMemorySize, SMEM_BYTES);
    edge_mlp_hmma<<<148, THREADS, SMEM_BYTES>>>(x, ei, ea, W1, b1, W2, b2, W3, b3, out, nE);
}

// round 4
// speedup vs baseline: 3.5683x; 1.1157x over previous
#include <cuda_runtime.h>
#include <cstdint>

// EdgePredictor, tf32 mma.sync + ldmatrix, 4 independent warp-pair pipelines per CTA.
// Pair p = warps {p, p+4} owns A rows 32p..32p+31 and processes its own stream of
// 32-edge tiles; only named pair barriers (bar.sync p+1, 64) inside the loop.
// Weights (tf32, transposed) staged once per persistent CTA; 148 CTAs x 256 threads.

#define THREADS 256
#define SA 132   // A row stride (words)
#define S1 260   // W1t row stride
#define S2 132   // W2t row stride

#define OFF_W1T  0u        // [128 n][260] tf32 : 133120 B
#define OFF_A    133120u   // [128 m][132] tf32 : 67584 B
#define OFF_W2T  200704u   // [32 n][132] tf32 : 16896 B
#define OFF_B1   217600u   // 128 f32
#define OFF_R256 218112u   // 128 f32
#define OFF_B2   218624u   // 32 f32
#define OFF_W3   218752u   // 32 f32
#define OFF_ATTR 218880u   // [4][32] f32
#define OFF_SRC  219392u   // [4][32] i32
#define OFF_DST  219904u   // [4][32] i32
#define SMEM_BYTES 220416

__device__ __forceinline__ uint32_t smem_u32(const void* p) {
    uint32_t a;
    asm("{ .reg .u64 t; cvta.to.shared.u64 t, %1; cvt.u32.u64 %0, t; }" : "=r"(a) : "l"(p));
    return a;
}
__device__ __forceinline__ uint32_t f2tf32(float f) {
    uint32_t r;
    asm("cvt.rn.tf32.f32 %0, %1;" : "=r"(r) : "f"(f));
    return r;
}
__device__ __forceinline__ void ldsm4(uint32_t* r, uint32_t a) {
    asm volatile("ldmatrix.sync.aligned.m8n8.x4.shared.b16 {%0,%1,%2,%3}, [%4];"
                 : "=r"(r[0]), "=r"(r[1]), "=r"(r[2]), "=r"(r[3]) : "r"(a));
}
__device__ __forceinline__ void ldsm2(uint32_t* r, uint32_t a) {
    asm volatile("ldmatrix.sync.aligned.m8n8.x2.shared.b16 {%0,%1}, [%2];"
                 : "=r"(r[0]), "=r"(r[1]) : "r"(a));
}
__device__ __forceinline__ void mma8(float* c, const uint32_t* a, const uint32_t* b) {
    asm volatile("mma.sync.aligned.m16n8k8.row.col.f32.tf32.tf32.f32 "
                 "{%0,%1,%2,%3}, {%4,%5,%6,%7}, {%8,%9}, {%0,%1,%2,%3};"
                 : "+f"(c[0]), "+f"(c[1]), "+f"(c[2]), "+f"(c[3])
                 : "r"(a[0]), "r"(a[1]), "r"(a[2]), "r"(a[3]), "r"(b[0]), "r"(b[1]));
}
__device__ __forceinline__ void barp(int id) {
    asm volatile("bar.sync %0, 64;" :: "r"(id) : "memory");
}

__global__ __launch_bounds__(THREADS, 1)
void edge_mlp_hmma(const float* __restrict__ x,
                   const int* __restrict__ ei,
                   const float* __restrict__ ea,
                   const float* __restrict__ W1g, const float* __restrict__ b1g,
                   const float* __restrict__ W2g, const float* __restrict__ b2g,
                   const float* __restrict__ W3g, const float* __restrict__ b3g,
                   float* __restrict__ out, int nE)
{
    extern __shared__ char smem[];
    const uint32_t sb = smem_u32(smem);
    const int tx = threadIdx.x;
    const int w  = tx >> 5;
    const int l  = tx & 31;
    const int pair = w & 3;          // pipeline id
    const int half = w >> 2;         // 0 or 1 within pair
    const int barid = pair + 1;

    uint32_t* W1t = (uint32_t*)(smem + OFF_W1T);
    uint32_t* W2t = (uint32_t*)(smem + OFF_W2T);
    float* b1s   = (float*)(smem + OFF_B1);
    float* r256s = (float*)(smem + OFF_R256);
    float* b2s   = (float*)(smem + OFF_B2);
    float* W3s   = (float*)(smem + OFF_W3);
    float* attrP = (float*)(smem + OFF_ATTR) + pair * 32;
    int*   srcP  = (int*)(smem + OFF_SRC) + pair * 32;
    int*   dstP  = (int*)(smem + OFF_DST) + pair * 32;

    // ---- one-time weight staging (tf32, transposed) ----
    for (int idx = tx; idx < 257 * 128; idx += THREADS) {
        int k = idx >> 7, n = idx & 127;
        float v = W1g[idx];
        if (k < 256) W1t[n * S1 + k] = f2tf32(v);
        else         r256s[n] = v;
    }
    for (int idx = tx; idx < 128 * 32; idx += THREADS) {
        int k = idx >> 5, n = idx & 31;
        W2t[n * S2 + k] = f2tf32(W2g[idx]);
    }
    if (tx < 128) b1s[tx] = b1g[tx];
    if (tx < 32)  { b2s[tx] = b2g[tx]; W3s[tx] = W3g[tx]; }
    const float b3v = b3g[0];
    __syncthreads();

    // ---- per-lane fragment bases ----
    const int g = l >> 2, t4 = l & 3;
    const int aSel = l & 15;
    const int aColB = (l >> 4) * 16;
    const int bRow = l & 7;
    const int bColB = ((l >> 3) & 1) * 16;

    const int m0 = pair * 32;         // pair's A-row block
    const int n0w = half * 64;        // layer-1 n slice per warp
    const uint32_t aBase0 = sb + OFF_A + (uint32_t)(m0 + aSel) * (SA * 4) + aColB;
    const uint32_t aBase1 = aBase0 + 16 * SA * 4;
    const uint32_t bBase1 = sb + OFF_W1T + (uint32_t)(n0w + bRow) * (S1 * 4) + bColB;
    const uint32_t aBase2 = sb + OFF_A + (uint32_t)(m0 + half * 16 + aSel) * (SA * 4) + aColB;
    const uint32_t bBase2 = sb + OFF_W2T + (uint32_t)bRow * (S2 * 4) + bColB;

    const float4* x4 = (const float4*)x;
    const int nT32 = (nE + 31) >> 5;
    const int stride = gridDim.x * 4;
    int t = blockIdx.x * 4 + pair;

    // ---- preamble: indices for first tile ----
    if (half == 0) {
        int e = t * 32 + l;
        bool v = (t < nT32) && (e < nE);
        srcP[l]  = v ? ei[e] : 0;
        dstP[l]  = v ? ei[nE + e] : 0;
        attrP[l] = v ? ea[e] : 0.f;
    }
    barp(barid);

    for (; t < nT32; t += stride) {
        const int base = t << 5;
        const int nt = t + stride;

        // prefetch next tile's indices into registers
        int nsrc = 0, ndst = 0; float nattr = 0.f;
        if (half == 0 && nt < nT32) {
            int e = nt * 32 + l;
            if (e < nE) { nsrc = ei[e]; ndst = ei[nE + e]; nattr = ea[e]; }
        }

        // ---- gather src feats: warp covers 16 of the pair's 32 rows ----
        #pragma unroll
        for (int r = 0; r < 16; r++) {
            int lr = half * 16 + r;
            float4 ft = x4[srcP[lr] * 32 + l];
            uint4 u = make_uint4(f2tf32(ft.x), f2tf32(ft.y), f2tf32(ft.z), f2tf32(ft.w));
            *(uint4*)(smem + OFF_A + (uint32_t)(m0 + lr) * (SA * 4) + l * 16) = u;
        }
        barp(barid);

        // prefetch dst feats into registers (lands during MMA half-0)
        float4 dbuf[16];
        #pragma unroll
        for (int r = 0; r < 16; r++)
            dbuf[r] = x4[dstP[half * 16 + r] * 32 + l];

        float acc[2][8][4];
        #pragma unroll
        for (int mi = 0; mi < 2; mi++)
            #pragma unroll
            for (int ni = 0; ni < 8; ni++)
                #pragma unroll
                for (int c = 0; c < 4; c++) acc[mi][ni][c] = 0.f;

        // ---- layer-1 half 0 ----
        #pragma unroll 4
        for (int ks = 0; ks < 16; ks++) {
            uint32_t a0[4], a1[4];
            ldsm4(a0, aBase0 + ks * 32);
            ldsm4(a1, aBase1 + ks * 32);
            #pragma unroll
            for (int ni = 0; ni < 8; ni++) {
                uint32_t b[2];
                ldsm2(b, bBase1 + ni * (8 * S1 * 4) + ks * 32);
                mma8(acc[0][ni], a0, b);
                mma8(acc[1][ni], a1, b);
            }
        }
        barp(barid);

        // ---- store dst feats -> A ----
        #pragma unroll
        for (int r = 0; r < 16; r++) {
            int lr = half * 16 + r;
            uint4 u = make_uint4(f2tf32(dbuf[r].x), f2tf32(dbuf[r].y),
                                 f2tf32(dbuf[r].z), f2tf32(dbuf[r].w));
            *(uint4*)(smem + OFF_A + (uint32_t)(m0 + lr) * (SA * 4) + l * 16) = u;
        }
        barp(barid);

        // ---- layer-1 half 1 ----
        #pragma unroll 4
        for (int ks = 0; ks < 16; ks++) {
            uint32_t a0[4], a1[4];
            ldsm4(a0, aBase0 + ks * 32);
            ldsm4(a1, aBase1 + ks * 32);
            #pragma unroll
            for (int ni = 0; ni < 8; ni++) {
                uint32_t b[2];
                ldsm2(b, bBase1 + ni * (8 * S1 * 4) + 512 + ks * 32);
                mma8(acc[0][ni], a0, b);
                mma8(acc[1][ni], a1, b);
            }
        }
        barp(barid);   // all LDSM reads of A done before h1 overwrite

        // ---- epilogue 1: h1 = relu(D1 + attr*r256 + b1) -> A ----
        {
            float aR[2][2];
            aR[0][0] = attrP[g];      aR[0][1] = attrP[8 + g];
            aR[1][0] = attrP[16 + g]; aR[1][1] = attrP[24 + g];
            #pragma unroll
            for (int mi = 0; mi < 2; mi++) {
                int row0 = m0 + mi * 16 + g;
                #pragma unroll
                for (int ni = 0; ni < 8; ni++) {
                    int col = n0w + ni * 8 + 2 * t4;
                    float2 bb = *(const float2*)(b1s + col);
                    float2 rr = *(const float2*)(r256s + col);
                    float h0 = fmaxf(acc[mi][ni][0] + aR[mi][0] * rr.x + bb.x, 0.f);
                    float h1 = fmaxf(acc[mi][ni][1] + aR[mi][0] * rr.y + bb.y, 0.f);
                    float h2 = fmaxf(acc[mi][ni][2] + aR[mi][1] * rr.x + bb.x, 0.f);
                    float h3 = fmaxf(acc[mi][ni][3] + aR[mi][1] * rr.y + bb.y, 0.f);
                    uint2 u0 = make_uint2(f2tf32(h0), f2tf32(h1));
                    uint2 u1 = make_uint2(f2tf32(h2), f2tf32(h3));
                    *(uint2*)(smem + OFF_A + (uint32_t)row0 * (SA * 4) + col * 4) = u0;
                    *(uint2*)(smem + OFF_A + (uint32_t)(row0 + 8) * (SA * 4) + col * 4) = u1;
                }
            }
        }
        barp(barid);

        // commit next tile's indices (all reads of current ones are done)
        if (half == 0 && nt < nT32) {
            srcP[l] = nsrc; dstP[l] = ndst; attrP[l] = nattr;
        }

        // ---- layer 2: [32 x 128] @ [128 x 32], warp = 16 rows x 32 n ----
        float acc2[4][4];
        #pragma unroll
        for (int ni = 0; ni < 4; ni++)
            #pragma unroll
            for (int c = 0; c < 4; c++) acc2[ni][c] = 0.f;

        #pragma unroll 4
        for (int ks = 0; ks < 16; ks++) {
            uint32_t a0[4];
            ldsm4(a0, aBase2 + ks * 32);
            #pragma unroll
            for (int ni = 0; ni < 4; ni++) {
                uint32_t b[2];
                ldsm2(b, bBase2 + ni * (8 * S2 * 4) + ks * 32);
                mma8(acc2[ni], a0, b);
            }
        }

        // ---- layer 3: relu(h2).W3 in-warp reduce + sigmoid ----
        {
            float p0 = 0.f, p1 = 0.f;
            #pragma unroll
            for (int ni = 0; ni < 4; ni++) {
                int col = ni * 8 + 2 * t4;
                float2 bb = *(const float2*)(b2s + col);
                float2 ww = *(const float2*)(W3s + col);
                p0 += fmaxf(acc2[ni][0] + bb.x, 0.f) * ww.x
                    + fmaxf(acc2[ni][1] + bb.y, 0.f) * ww.y;
                p1 += fmaxf(acc2[ni][2] + bb.x, 0.f) * ww.x
                    + fmaxf(acc2[ni][3] + bb.y, 0.f) * ww.y;
            }
            p0 += __shfl_xor_sync(0xffffffffu, p0, 1, 4);
            p0 += __shfl_xor_sync(0xffffffffu, p0, 2, 4);
            p1 += __shfl_xor_sync(0xffffffffu, p1, 1, 4);
            p1 += __shfl_xor_sync(0xffffffffu, p1, 2, 4);
            if (t4 == 0) {
                int e0 = base + half * 16 + g;
                int e1 = e0 + 8;
                if (e0 < nE) out[e0] = 1.f / (1.f + __expf(-(p0 + b3v)));
                if (e1 < nE) out[e1] = 1.f / (1.f + __expf(-(p1 + b3v)));
            }
        }
        barp(barid);   // A + idx reused next tile
    }
}

extern "C" void kernel_launch(void* const* d_in, const int* in_sizes, int n_in,
                              void* d_out, int out_size)
{
    const float* x  = (const float*)d_in[0];
    const int*   ei = (const int*)d_in[1];
    const float* ea = (const float*)d_in[2];
    const float* W1 = (const float*)d_in[3];
    const float* b1 = (const float*)d_in[4];
    const float* W2 = (const float*)d_in[5];
    const float* b2 = (const float*)d_in[6];
    const float* W3 = (const float*)d_in[7];
    const float* b3 = (const float*)d_in[8];
    float* out = (float*)d_out;
    const int nE = out_size;

    cudaFuncSetAttribute(edge_mlp_hmma,
                         cudaFuncAttributeMaxDynamicSharedMemorySize, SMEM_BYTES);
    edge_mlp_hmma<<<148, THREADS, SMEM_BYTES>>>(x, ei, ea, W1, b1, W2, b2, W3, b3, out, nE);
}

// round 6
// speedup vs baseline: 3.6031x; 1.0097x over previous
#include <cuda_runtime.h>
#include <cstdint>

// EdgePredictor, tf32 mma.sync + ldmatrix, 4 independent warp-pair pipelines per CTA.
// R5: pair p = warps {2p, 2p+1}  ->  the two warps of a pipeline land on DIFFERENT
// SMSPs, and each SMSP hosts warps from two different pipelines. Tensor units get
// fed by whichever pipeline is in its MMA phase (phase decorrelation).
// Weights (tf32, transposed) staged once per persistent CTA; 148 CTAs x 256 threads.

#define THREADS 256
#define SA 132   // A row stride (words)
#define S1 260   // W1t row stride
#define S2 132   // W2t row stride

#define OFF_W1T  0u        // [128 n][260] tf32 : 133120 B
#define OFF_A    133120u   // [128 m][132] tf32 : 67584 B
#define OFF_W2T  200704u   // [32 n][132] tf32 : 16896 B
#define OFF_B1   217600u   // 128 f32
#define OFF_R256 218112u   // 128 f32
#define OFF_B2   218624u   // 32 f32
#define OFF_W3   218752u   // 32 f32
#define OFF_ATTR 218880u   // [4][32] f32
#define OFF_SRC  219392u   // [4][32] i32
#define OFF_DST  219904u   // [4][32] i32
#define SMEM_BYTES 220416

__device__ __forceinline__ uint32_t smem_u32(const void* p) {
    uint32_t a;
    asm("{ .reg .u64 t; cvta.to.shared.u64 t, %1; cvt.u32.u64 %0, t; }" : "=r"(a) : "l"(p));
    return a;
}
__device__ __forceinline__ uint32_t f2tf32(float f) {
    uint32_t r;
    asm("cvt.rn.tf32.f32 %0, %1;" : "=r"(r) : "f"(f));
    return r;
}
__device__ __forceinline__ void ldsm4(uint32_t* r, uint32_t a) {
    asm volatile("ldmatrix.sync.aligned.m8n8.x4.shared.b16 {%0,%1,%2,%3}, [%4];"
                 : "=r"(r[0]), "=r"(r[1]), "=r"(r[2]), "=r"(r[3]) : "r"(a));
}
__device__ __forceinline__ void ldsm2(uint32_t* r, uint32_t a) {
    asm volatile("ldmatrix.sync.aligned.m8n8.x2.shared.b16 {%0,%1}, [%2];"
                 : "=r"(r[0]), "=r"(r[1]) : "r"(a));
}
__device__ __forceinline__ void mma8(float* c, const uint32_t* a, const uint32_t* b) {
    asm volatile("mma.sync.aligned.m16n8k8.row.col.f32.tf32.tf32.f32 "
                 "{%0,%1,%2,%3}, {%4,%5,%6,%7}, {%8,%9}, {%0,%1,%2,%3};"
                 : "+f"(c[0]), "+f"(c[1]), "+f"(c[2]), "+f"(c[3])
                 : "r"(a[0]), "r"(a[1]), "r"(a[2]), "r"(a[3]), "r"(b[0]), "r"(b[1]));
}
__device__ __forceinline__ void barp(int id) {
    asm volatile("bar.sync %0, 64;" :: "r"(id) : "memory");
}

__global__ __launch_bounds__(THREADS, 1)
void edge_mlp_hmma(const float* __restrict__ x,
                   const int* __restrict__ ei,
                   const float* __restrict__ ea,
                   const float* __restrict__ W1g, const float* __restrict__ b1g,
                   const float* __restrict__ W2g, const float* __restrict__ b2g,
                   const float* __restrict__ W3g, const float* __restrict__ b3g,
                   float* __restrict__ out, int nE)
{
    extern __shared__ char smem[];
    const uint32_t sb = smem_u32(smem);
    const int tx = threadIdx.x;
    const int w  = tx >> 5;
    const int l  = tx & 31;
    const int pair = w >> 1;         // pipeline id: warps {2p, 2p+1} -> SMSPs {2p%4, (2p+1)%4}
    const int half = w & 1;          // 0 or 1 within pair
    const int barid = pair + 1;

    uint32_t* W1t = (uint32_t*)(smem + OFF_W1T);
    uint32_t* W2t = (uint32_t*)(smem + OFF_W2T);
    float* b1s   = (float*)(smem + OFF_B1);
    float* r256s = (float*)(smem + OFF_R256);
    float* b2s   = (float*)(smem + OFF_B2);
    float* W3s   = (float*)(smem + OFF_W3);
    float* attrP = (float*)(smem + OFF_ATTR) + pair * 32;
    int*   srcP  = (int*)(smem + OFF_SRC) + pair * 32;
    int*   dstP  = (int*)(smem + OFF_DST) + pair * 32;

    // ---- one-time weight staging (tf32, transposed) ----
    for (int idx = tx; idx < 257 * 128; idx += THREADS) {
        int k = idx >> 7, n = idx & 127;
        float v = W1g[idx];
        if (k < 256) W1t[n * S1 + k] = f2tf32(v);
        else         r256s[n] = v;
    }
    for (int idx = tx; idx < 128 * 32; idx += THREADS) {
        int k = idx >> 5, n = idx & 31;
        W2t[n * S2 + k] = f2tf32(W2g[idx]);
    }
    if (tx < 128) b1s[tx] = b1g[tx];
    if (tx < 32)  { b2s[tx] = b2g[tx]; W3s[tx] = W3g[tx]; }
    const float b3v = b3g[0];
    __syncthreads();

    // ---- per-lane fragment bases ----
    const int g = l >> 2, t4 = l & 3;
    const int aSel = l & 15;
    const int aColB = (l >> 4) * 16;
    const int bRow = l & 7;
    const int bColB = ((l >> 3) & 1) * 16;

    const int m0 = pair * 32;         // pair's A-row block
    const int n0w = half * 64;        // layer-1 n slice per warp
    const uint32_t aBase0 = sb + OFF_A + (uint32_t)(m0 + aSel) * (SA * 4) + aColB;
    const uint32_t aBase1 = aBase0 + 16 * SA * 4;
    const uint32_t bBase1 = sb + OFF_W1T + (uint32_t)(n0w + bRow) * (S1 * 4) + bColB;
    const uint32_t aBase2 = sb + OFF_A + (uint32_t)(m0 + half * 16 + aSel) * (SA * 4) + aColB;
    const uint32_t bBase2 = sb + OFF_W2T + (uint32_t)bRow * (S2 * 4) + bColB;

    const float4* x4 = (const float4*)x;
    const int nT32 = (nE + 31) >> 5;
    const int stride = gridDim.x * 4;
    int t = blockIdx.x * 4 + pair;

    // ---- preamble: indices for first tile ----
    if (half == 0) {
        int e = t * 32 + l;
        bool v = (t < nT32) && (e < nE);
        srcP[l]  = v ? ei[e] : 0;
        dstP[l]  = v ? ei[nE + e] : 0;
        attrP[l] = v ? ea[e] : 0.f;
    }
    barp(barid);

    for (; t < nT32; t += stride) {
        const int base = t << 5;
        const int nt = t + stride;

        // prefetch next tile's indices into registers
        int nsrc = 0, ndst = 0; float nattr = 0.f;
        if (half == 0 && nt < nT32) {
            int e = nt * 32 + l;
            if (e < nE) { nsrc = ei[e]; ndst = ei[nE + e]; nattr = ea[e]; }
        }

        // ---- gather src feats: warp covers 16 of the pair's 32 rows ----
        #pragma unroll
        for (int r = 0; r < 16; r++) {
            int lr = half * 16 + r;
            float4 ft = x4[srcP[lr] * 32 + l];
            uint4 u = make_uint4(f2tf32(ft.x), f2tf32(ft.y), f2tf32(ft.z), f2tf32(ft.w));
            *(uint4*)(smem + OFF_A + (uint32_t)(m0 + lr) * (SA * 4) + l * 16) = u;
        }
        barp(barid);

        // prefetch dst feats into registers (lands during MMA half-0)
        float4 dbuf[16];
        #pragma unroll
        for (int r = 0; r < 16; r++)
            dbuf[r] = x4[dstP[half * 16 + r] * 32 + l];

        float acc[2][8][4];
        #pragma unroll
        for (int mi = 0; mi < 2; mi++)
            #pragma unroll
            for (int ni = 0; ni < 8; ni++)
                #pragma unroll
                for (int c = 0; c < 4; c++) acc[mi][ni][c] = 0.f;

        // ---- layer-1 half 0 ----
        #pragma unroll 4
        for (int ks = 0; ks < 16; ks++) {
            uint32_t a0[4], a1[4];
            ldsm4(a0, aBase0 + ks * 32);
            ldsm4(a1, aBase1 + ks * 32);
            #pragma unroll
            for (int ni = 0; ni < 8; ni++) {
                uint32_t b[2];
                ldsm2(b, bBase1 + ni * (8 * S1 * 4) + ks * 32);
                mma8(acc[0][ni], a0, b);
                mma8(acc[1][ni], a1, b);
            }
        }
        barp(barid);

        // ---- store dst feats -> A ----
        #pragma unroll
        for (int r = 0; r < 16; r++) {
            int lr = half * 16 + r;
            uint4 u = make_uint4(f2tf32(dbuf[r].x), f2tf32(dbuf[r].y),
                                 f2tf32(dbuf[r].z), f2tf32(dbuf[r].w));
            *(uint4*)(smem + OFF_A + (uint32_t)(m0 + lr) * (SA * 4) + l * 16) = u;
        }
        barp(barid);

        // ---- layer-1 half 1 ----
        #pragma unroll 4
        for (int ks = 0; ks < 16; ks++) {
            uint32_t a0[4], a1[4];
            ldsm4(a0, aBase0 + ks * 32);
            ldsm4(a1, aBase1 + ks * 32);
            #pragma unroll
            for (int ni = 0; ni < 8; ni++) {
                uint32_t b[2];
                ldsm2(b, bBase1 + ni * (8 * S1 * 4) + 512 + ks * 32);
                mma8(acc[0][ni], a0, b);
                mma8(acc[1][ni], a1, b);
            }
        }
        barp(barid);   // all LDSM reads of A done before h1 overwrite

        // ---- epilogue 1: h1 = relu(D1 + attr*r256 + b1) -> A ----
        {
            float aR[2][2];
            aR[0][0] = attrP[g];      aR[0][1] = attrP[8 + g];
            aR[1][0] = attrP[16 + g]; aR[1][1] = attrP[24 + g];
            #pragma unroll
            for (int mi = 0; mi < 2; mi++) {
                int row0 = m0 + mi * 16 + g;
                #pragma unroll
                for (int ni = 0; ni < 8; ni++) {
                    int col = n0w + ni * 8 + 2 * t4;
                    float2 bb = *(const float2*)(b1s + col);
                    float2 rr = *(const float2*)(r256s + col);
                    float h0 = fmaxf(acc[mi][ni][0] + aR[mi][0] * rr.x + bb.x, 0.f);
                    float h1 = fmaxf(acc[mi][ni][1] + aR[mi][0] * rr.y + bb.y, 0.f);
                    float h2 = fmaxf(acc[mi][ni][2] + aR[mi][1] * rr.x + bb.x, 0.f);
                    float h3 = fmaxf(acc[mi][ni][3] + aR[mi][1] * rr.y + bb.y, 0.f);
                    uint2 u0 = make_uint2(f2tf32(h0), f2tf32(h1));
                    uint2 u1 = make_uint2(f2tf32(h2), f2tf32(h3));
                    *(uint2*)(smem + OFF_A + (uint32_t)row0 * (SA * 4) + col * 4) = u0;
                    *(uint2*)(smem + OFF_A + (uint32_t)(row0 + 8) * (SA * 4) + col * 4) = u1;
                }
            }
        }
        barp(barid);

        // commit next tile's indices (all reads of current ones are done)
        if (half == 0 && nt < nT32) {
            srcP[l] = nsrc; dstP[l] = ndst; attrP[l] = nattr;
        }

        // ---- layer 2: [32 x 128] @ [128 x 32], warp = 16 rows x 32 n ----
        float acc2[4][4];
        #pragma unroll
        for (int ni = 0; ni < 4; ni++)
            #pragma unroll
            for (int c = 0; c < 4; c++) acc2[ni][c] = 0.f;

        #pragma unroll 4
        for (int ks = 0; ks < 16; ks++) {
            uint32_t a0[4];
            ldsm4(a0, aBase2 + ks * 32);
            #pragma unroll
            for (int ni = 0; ni < 4; ni++) {
                uint32_t b[2];
                ldsm2(b, bBase2 + ni * (8 * S2 * 4) + ks * 32);
                mma8(acc2[ni], a0, b);
            }
        }

        // ---- layer 3: relu(h2).W3 in-warp reduce + sigmoid ----
        {
            float p0 = 0.f, p1 = 0.f;
            #pragma unroll
            for (int ni = 0; ni < 4; ni++) {
                int col = ni * 8 + 2 * t4;
                float2 bb = *(const float2*)(b2s + col);
                float2 ww = *(const float2*)(W3s + col);
                p0 += fmaxf(acc2[ni][0] + bb.x, 0.f) * ww.x
                    + fmaxf(acc2[ni][1] + bb.y, 0.f) * ww.y;
                p1 += fmaxf(acc2[ni][2] + bb.x, 0.f) * ww.x
                    + fmaxf(acc2[ni][3] + bb.y, 0.f) * ww.y;
            }
            p0 += __shfl_xor_sync(0xffffffffu, p0, 1, 4);
            p0 += __shfl_xor_sync(0xffffffffu, p0, 2, 4);
            p1 += __shfl_xor_sync(0xffffffffu, p1, 1, 4);
            p1 += __shfl_xor_sync(0xffffffffu, p1, 2, 4);
            if (t4 == 0) {
                int e0 = base + half * 16 + g;
                int e1 = e0 + 8;
                if (e0 < nE) out[e0] = 1.f / (1.f + __expf(-(p0 + b3v)));
                if (e1 < nE) out[e1] = 1.f / (1.f + __expf(-(p1 + b3v)));
            }
        }
        barp(barid);   // A + idx reused next tile
    }
}

extern "C" void kernel_launch(void* const* d_in, const int* in_sizes, int n_in,
                              void* d_out, int out_size)
{
    const float* x  = (const float*)d_in[0];
    const int*   ei = (const int*)d_in[1];
    const float* ea = (const float*)d_in[2];
    const float* W1 = (const float*)d_in[3];
    const float* b1 = (const float*)d_in[4];
    const float* W2 = (const float*)d_in[5];
    const float* b2 = (const float*)d_in[6];
    const float* W3 = (const float*)d_in[7];
    const float* b3 = (const float*)d_in[8];
    float* out = (float*)d_out;
    const int nE = out_size;

    cudaFuncSetAttribute(edge_mlp_hmma,
                         cudaFuncAttributeMaxDynamicSharedMemorySize, SMEM_BYTES);
    edge_mlp_hmma<<<148, THREADS, SMEM_BYTES>>>(x, ei, ea, W1, b1, W2, b2, W3, b3, out, nE);
}

// round 7
// speedup vs baseline: 7.7835x; 2.1602x over previous
#include <cuda_runtime.h>
#include <cuda_fp16.h>
#include <cstdint>

// EdgePredictor, fp16 mma.sync.m16n8k16 + ldmatrix, 16 independent single-warp
// pipelines per CTA (512 thr). Warp w owns A rows [16w,16w+16) and a private
// stream of 16-edge tiles; no block/named barriers in the loop, only __syncwarp.
// Weights staged once (fp16, transposed) per persistent CTA; 148 CTAs.

#define THREADS 512
#define A_ROW  272u   // 136 halves
#define W1_ROW 528u   // 264 halves
#define W2_ROW 272u

#define OFF_W1T  0u        // [128 n][264 h] : 67584 B
#define OFF_A    67584u    // 16 warps x 16 rows x 272 B : 69632 B
#define OFF_W2T  137216u   // [32 n][136 h] : 8704 B
#define OFF_B1   145920u   // 128 f32
#define OFF_R256 146432u   // 128 f32
#define OFF_B2   146944u   // 32 f32
#define OFF_W3   147072u   // 32 f32
#define SMEM_BYTES 147200

__device__ __forceinline__ uint32_t smem_u32(const void* p) {
    uint32_t a;
    asm("{ .reg .u64 t; cvta.to.shared.u64 t, %1; cvt.u32.u64 %0, t; }" : "=r"(a) : "l"(p));
    return a;
}
__device__ __forceinline__ void ldsm4(uint32_t* r, uint32_t a) {
    asm volatile("ldmatrix.sync.aligned.m8n8.x4.shared.b16 {%0,%1,%2,%3}, [%4];"
                 : "=r"(r[0]), "=r"(r[1]), "=r"(r[2]), "=r"(r[3]) : "r"(a));
}
__device__ __forceinline__ void mma16(float* c, const uint32_t* a, uint32_t b0, uint32_t b1) {
    asm volatile("mma.sync.aligned.m16n8k16.row.col.f32.f16.f16.f32 "
                 "{%0,%1,%2,%3}, {%4,%5,%6,%7}, {%8,%9}, {%0,%1,%2,%3};"
                 : "+f"(c[0]), "+f"(c[1]), "+f"(c[2]), "+f"(c[3])
                 : "r"(a[0]), "r"(a[1]), "r"(a[2]), "r"(a[3]), "r"(b0), "r"(b1));
}
__device__ __forceinline__ uint32_t pack_h2(float a, float b) {
    __half2 h = __floats2half2_rn(a, b);
    return *(const uint32_t*)&h;
}

__global__ __launch_bounds__(THREADS, 1)
void edge_mlp_fp16(const float* __restrict__ x,
                   const int* __restrict__ ei,
                   const float* __restrict__ ea,
                   const float* __restrict__ W1g, const float* __restrict__ b1g,
                   const float* __restrict__ W2g, const float* __restrict__ b2g,
                   const float* __restrict__ W3g, const float* __restrict__ b3g,
                   float* __restrict__ out, int nE)
{
    extern __shared__ char smem[];
    const uint32_t sb = smem_u32(smem);
    const int tx = threadIdx.x;
    const int w  = tx >> 5;
    const int l  = tx & 31;

    float* b1s   = (float*)(smem + OFF_B1);
    float* r256s = (float*)(smem + OFF_R256);
    float* b2s   = (float*)(smem + OFF_B2);
    float* W3s   = (float*)(smem + OFF_W3);

    // ---- one-time weight staging (fp16, transposed) ----
    for (int idx = tx; idx < 257 * 128; idx += THREADS) {
        int k = idx >> 7, n = idx & 127;
        float v = W1g[idx];
        if (k < 256) *(__half*)(smem + OFF_W1T + n * W1_ROW + k * 2) = __float2half_rn(v);
        else         r256s[n] = v;
    }
    for (int idx = tx; idx < 128 * 32; idx += THREADS) {
        int k = idx >> 5, n = idx & 31;
        *(__half*)(smem + OFF_W2T + n * W2_ROW + k * 2) = __float2half_rn(W2g[idx]);
    }
    if (tx < 128) b1s[tx] = b1g[tx];
    if (tx < 32)  { b2s[tx] = b2g[tx]; W3s[tx] = W3g[tx]; }
    const float b3v = b3g[0];
    __syncthreads();

    // ---- per-lane fragment bases ----
    const int g  = l >> 2, t4 = l & 3;
    const int aSel  = l & 15;
    const int aColB = (l >> 4) * 16;
    const int bR = (l & 7) + ((l >> 4) & 1) * 8;
    const int bC = ((l >> 3) & 1) * 16;

    const uint32_t aWarp = sb + OFF_A + (uint32_t)w * 16 * A_ROW;   // warp's 16-row strip
    const uint32_t aBase = aWarp + (uint32_t)aSel * A_ROW + aColB;
    const uint32_t bBase1 = sb + OFF_W1T + (uint32_t)bR * W1_ROW + bC;
    const uint32_t bBase2 = sb + OFF_W2T + (uint32_t)bR * W2_ROW + bC;

    const float4* x4 = (const float4*)x;
    const int nT = (nE + 15) >> 4;
    const int stride = gridDim.x * 16;

    for (int t = blockIdx.x * 16 + w; t < nT; t += stride) {
        const int base = t << 4;

        // ---- per-tile indices in registers (lanes 0..15) ----
        int srcR = 0, dstR = 0; float attrR = 0.f;
        if (l < 16) {
            int e = base + l;
            if (e < nE) { srcR = ei[e]; dstR = ei[nE + e]; attrR = ea[e]; }
        }

        // ---- gather src feats -> A strip (fp16) ----
        #pragma unroll
        for (int r = 0; r < 16; r++) {
            int node = __shfl_sync(0xffffffffu, srcR, r);
            float4 ft = x4[node * 32 + l];
            uint2 u = make_uint2(pack_h2(ft.x, ft.y), pack_h2(ft.z, ft.w));
            *(uint2*)(smem + (aWarp - sb) + (uint32_t)r * A_ROW + l * 8) = u;
        }
        __syncwarp();

        float acc[16][4];
        #pragma unroll
        for (int ni = 0; ni < 16; ni++)
            #pragma unroll
            for (int c = 0; c < 4; c++) acc[ni][c] = 0.f;

        // ---- layer-1 half 0: src feats vs W1 k[0..128) ----
        #pragma unroll
        for (int ks = 0; ks < 8; ks++) {
            uint32_t a[4];
            ldsm4(a, aBase + ks * 32);
            #pragma unroll
            for (int nip = 0; nip < 8; nip++) {
                uint32_t b[4];
                ldsm4(b, bBase1 + nip * (16 * W1_ROW) + ks * 32);
                mma16(acc[2 * nip],     a, b[0], b[1]);
                mma16(acc[2 * nip + 1], a, b[2], b[3]);
            }
        }
        __syncwarp();   // LDSM reads of src done before overwrite

        // ---- gather dst feats -> A strip ----
        #pragma unroll
        for (int r = 0; r < 16; r++) {
            int node = __shfl_sync(0xffffffffu, dstR, r);
            float4 ft = x4[node * 32 + l];
            uint2 u = make_uint2(pack_h2(ft.x, ft.y), pack_h2(ft.z, ft.w));
            *(uint2*)(smem + (aWarp - sb) + (uint32_t)r * A_ROW + l * 8) = u;
        }
        __syncwarp();

        // ---- layer-1 half 1: dst feats vs W1 k[128..256) ----
        #pragma unroll
        for (int ks = 0; ks < 8; ks++) {
            uint32_t a[4];
            ldsm4(a, aBase + ks * 32);
            #pragma unroll
            for (int nip = 0; nip < 8; nip++) {
                uint32_t b[4];
                ldsm4(b, bBase1 + nip * (16 * W1_ROW) + 256 + ks * 32);
                mma16(acc[2 * nip],     a, b[0], b[1]);
                mma16(acc[2 * nip + 1], a, b[2], b[3]);
            }
        }
        __syncwarp();   // LDSM reads done before h1 overwrite

        // ---- epilogue 1: h1 = relu(D1 + attr*r256 + b1) -> A strip (fp16) ----
        {
            const float am0 = __shfl_sync(0xffffffffu, attrR, g);
            const float am1 = __shfl_sync(0xffffffffu, attrR, g + 8);
            #pragma unroll
            for (int ni = 0; ni < 16; ni++) {
                int col = ni * 8 + 2 * t4;
                float2 bb = *(const float2*)(b1s + col);
                float2 rr = *(const float2*)(r256s + col);
                float h0 = fmaxf(acc[ni][0] + am0 * rr.x + bb.x, 0.f);
                float h1 = fmaxf(acc[ni][1] + am0 * rr.y + bb.y, 0.f);
                float h2 = fmaxf(acc[ni][2] + am1 * rr.x + bb.x, 0.f);
                float h3 = fmaxf(acc[ni][3] + am1 * rr.y + bb.y, 0.f);
                *(uint32_t*)(smem + (aWarp - sb) + (uint32_t)g * A_ROW + col * 2) = pack_h2(h0, h1);
                *(uint32_t*)(smem + (aWarp - sb) + (uint32_t)(g + 8) * A_ROW + col * 2) = pack_h2(h2, h3);
            }
        }
        __syncwarp();

        // ---- layer 2: [16 x 128] @ [128 x 32] ----
        float acc2[4][4];
        #pragma unroll
        for (int ni = 0; ni < 4; ni++)
            #pragma unroll
            for (int c = 0; c < 4; c++) acc2[ni][c] = 0.f;

        #pragma unroll
        for (int ks = 0; ks < 8; ks++) {
            uint32_t a[4];
            ldsm4(a, aBase + ks * 32);
            #pragma unroll
            for (int nip = 0; nip < 2; nip++) {
                uint32_t b[4];
                ldsm4(b, bBase2 + nip * (16 * W2_ROW) + ks * 32);
                mma16(acc2[2 * nip],     a, b[0], b[1]);
                mma16(acc2[2 * nip + 1], a, b[2], b[3]);
            }
        }

        // ---- layer 3: relu(h2).W3 reduce(width4) + sigmoid ----
        {
            float p0 = 0.f, p1 = 0.f;
            #pragma unroll
            for (int ni = 0; ni < 4; ni++) {
                int col = ni * 8 + 2 * t4;
                float2 bb = *(const float2*)(b2s + col);
                float2 ww = *(const float2*)(W3s + col);
                p0 += fmaxf(acc2[ni][0] + bb.x, 0.f) * ww.x
                    + fmaxf(acc2[ni][1] + bb.y, 0.f) * ww.y;
                p1 += fmaxf(acc2[ni][2] + bb.x, 0.f) * ww.x
                    + fmaxf(acc2[ni][3] + bb.y, 0.f) * ww.y;
            }
            p0 += __shfl_xor_sync(0xffffffffu, p0, 1, 4);
            p0 += __shfl_xor_sync(0xffffffffu, p0, 2, 4);
            p1 += __shfl_xor_sync(0xffffffffu, p1, 1, 4);
            p1 += __shfl_xor_sync(0xffffffffu, p1, 2, 4);
            if (t4 == 0) {
                int e0 = base + g, e1 = base + g + 8;
                if (e0 < nE) out[e0] = 1.f / (1.f + __expf(-(p0 + b3v)));
                if (e1 < nE) out[e1] = 1.f / (1.f + __expf(-(p1 + b3v)));
            }
        }
        __syncwarp();   // L2 LDSM done before next tile's gather overwrite
    }
}

extern "C" void kernel_launch(void* const* d_in, const int* in_sizes, int n_in,
                              void* d_out, int out_size)
{
    const float* x  = (const float*)d_in[0];
    const int*   ei = (const int*)d_in[1];
    const float* ea = (const float*)d_in[2];
    const float* W1 = (const float*)d_in[3];
    const float* b1 = (const float*)d_in[4];
    const float* W2 = (const float*)d_in[5];
    const float* b2 = (const float*)d_in[6];
    const float* W3 = (const float*)d_in[7];
    const float* b3 = (const float*)d_in[8];
    float* out = (float*)d_out;
    const int nE = out_size;

    cudaFuncSetAttribute(edge_mlp_fp16,
                         cudaFuncAttributeMaxDynamicSharedMemorySize, SMEM_BYTES);
    edge_mlp_fp16<<<148, THREADS, SMEM_BYTES>>>(x, ei, ea, W1, b1, W2, b2, W3, b3, out, nE);
}